// round 2
// baseline (speedup 1.0000x reference)
#include <cuda_runtime.h>
#include <cuda_bf16.h>

// Problem constants
#define M_TOTAL 16384   // 16 * 1024 query rows
#define N_CODES 8192
#define K_DIM   256
#define NUMEL   (M_TOTAL * K_DIM)   // 4194304

// GEMM tiling
#define BM 64
#define BN 128
#define BK 16
#define TM 8
#define TN 8
#define NTHREADS 128   // 16 x 8 thread grid (tx in [0,16), ty in [0,8))

// Scratch (no device allocation allowed)
__device__ float  g_esq[N_CODES];
__device__ float  g_qsq[M_TOTAL];
__device__ int    g_idx[M_TOTAL];
__device__ double g_loss;

// ---------------------------------------------------------------------------
// Kernel 1a: e_sq[n] = sum_c embedding[n][c]^2 ; also zero the loss accumulator
// grid: (N_CODES/8) blocks of dim3(32,8) — one warp per code row
// e_sq's own rounding error (~1e-8) is negligible vs ulp(256)=1.5e-5, any order ok.
// ---------------------------------------------------------------------------
__global__ void esq_kernel(const float* __restrict__ emb) {
    if (blockIdx.x == 0 && threadIdx.x == 0 && threadIdx.y == 0) {
        g_loss = 0.0;
    }
    int row = blockIdx.x * 8 + threadIdx.y;
    const float* e = emb + (size_t)row * K_DIM;
    // XLA-GPU-style row reduce: lane handles k = lane + 32*j, sequential adds,
    // then shfl_down tree. (Bit-exact match attempt with reference order.)
    float s = 0.0f;
    #pragma unroll
    for (int j = 0; j < K_DIM / 32; j++) {
        float v = e[threadIdx.x + 32 * j];
        s = __fadd_rn(s, __fmul_rn(v, v));
    }
    #pragma unroll
    for (int o = 16; o > 0; o >>= 1)
        s = __fadd_rn(s, __shfl_down_sync(0xffffffffu, s, o));
    if (threadIdx.x == 0) g_esq[row] = s;
}

// ---------------------------------------------------------------------------
// Kernel 1b: q_sq[m] = sum_c queries[m][c]^2 — THE precision-critical term.
// Its summation-order error (~1-10 ulp of 256) shifts the whole distance row
// before the reference's f32 grid rounding, which decides near-tie cells.
// Use the XLA GPU row-reduction order: strided sequential per lane, warp tree.
// ---------------------------------------------------------------------------
__global__ void qsq_kernel(const float* __restrict__ q) {
    int row = blockIdx.x * 8 + threadIdx.y;
    const float* x = q + (size_t)row * K_DIM;
    float s = 0.0f;
    #pragma unroll
    for (int j = 0; j < K_DIM / 32; j++) {
        float v = x[threadIdx.x + 32 * j];
        s = __fadd_rn(s, __fmul_rn(v, v));
    }
    #pragma unroll
    for (int o = 16; o > 0; o >>= 1)
        s = __fadd_rn(s, __shfl_down_sync(0xffffffffu, s, o));
    if (threadIdx.x == 0) g_qsq[row] = s;
}

// ---------------------------------------------------------------------------
// Kernel 2: fused distance GEMM + per-row argmin.
// dist(m,n) emulates the reference's f32 rounding pipeline exactly:
//   d = fsub_rn( fadd_rn(q_sq[m], e_sq[n]), 2*dot )
// so grid-level ties resolve to the same cells the reference saw, and the
// argmin tie-break (lowest index) matches jnp.argmin's first-occurrence rule.
// ---------------------------------------------------------------------------
__global__ __launch_bounds__(NTHREADS) void argmin_kernel(
    const float* __restrict__ Q,
    const float* __restrict__ E,
    float* __restrict__ out_idx_f)
{
    __shared__ float As[K_DIM][BM];     // 64 KB, transposed: As[k][row]
    __shared__ float Bs[BK][BN];        // 8 KB,  transposed: Bs[k][col]
    __shared__ float sEsq[BN];
    __shared__ float sQsq[BM];
    __shared__ float redv[BM][17];      // argmin reduction (padded)
    __shared__ int   redi[BM][17];

    const int tid = threadIdx.x;
    const int m0  = blockIdx.x * BM;

    // Stage full Q tile: 64 rows x 64 float4 = 4096 float4, 32 per thread.
    {
        const float4* Qv = (const float4*)(Q + (size_t)m0 * K_DIM);
        for (int i = tid; i < BM * (K_DIM / 4); i += NTHREADS) {
            int row = i / (K_DIM / 4);
            int seg = i % (K_DIM / 4);
            float4 v = Qv[row * (K_DIM / 4) + seg];
            As[seg * 4 + 0][row] = v.x;
            As[seg * 4 + 1][row] = v.y;
            As[seg * 4 + 2][row] = v.z;
            As[seg * 4 + 3][row] = v.w;
        }
        if (tid < BM) sQsq[tid] = g_qsq[m0 + tid];
    }

    const int tx = tid % 16;           // column group
    const int ty = tid / 16;           // row group

    float bestv[TM];
    int   besti[TM];
    #pragma unroll
    for (int i = 0; i < TM; i++) { bestv[i] = 3.4e38f; besti[i] = 0; }

    for (int n0 = 0; n0 < N_CODES; n0 += BN) {
        __syncthreads();               // protect sEsq/Bs from previous readers
        sEsq[tid] = g_esq[n0 + tid];   // NTHREADS == BN

        float acc[TM][TN];
        #pragma unroll
        for (int i = 0; i < TM; i++)
            #pragma unroll
            for (int j = 0; j < TN; j++) acc[i][j] = 0.0f;

        for (int k0 = 0; k0 < K_DIM; k0 += BK) {
            __syncthreads();
            // Load B tile: BN rows x BK cols = 512 float4, 4 per thread.
            for (int i = tid; i < BN * (BK / 4); i += NTHREADS) {
                int row = i / (BK / 4);
                int seg = i % (BK / 4);
                float4 v = *(const float4*)(E + (size_t)(n0 + row) * K_DIM + k0 + seg * 4);
                Bs[seg * 4 + 0][row] = v.x;
                Bs[seg * 4 + 1][row] = v.y;
                Bs[seg * 4 + 2][row] = v.z;
                Bs[seg * 4 + 3][row] = v.w;
            }
            __syncthreads();

            #pragma unroll
            for (int k = 0; k < BK; k++) {
                float a[TM], b[TN];
                #pragma unroll
                for (int i = 0; i < TM; i++) a[i] = As[k0 + k][ty * TM + i];
                #pragma unroll
                for (int j = 0; j < TN; j++) b[j] = Bs[k][tx * TN + j];
                #pragma unroll
                for (int i = 0; i < TM; i++)
                    #pragma unroll
                    for (int j = 0; j < TN; j++)
                        acc[i][j] = fmaf(a[i], b[j], acc[i][j]);
            }
        }

        // Fused argmin epilogue over this BN chunk — reference grid emulation.
        #pragma unroll
        for (int i = 0; i < TM; i++) {
            float qs = sQsq[ty * TM + i];
            #pragma unroll
            for (int j = 0; j < TN; j++) {
                float d  = __fsub_rn(__fadd_rn(qs, sEsq[tx * TN + j]),
                                     2.0f * acc[i][j]);
                int   ix = n0 + tx * TN + j;
                // strict less: on exact grid ties the earlier (lower) index wins
                if (d < bestv[i] || (d == bestv[i] && ix < besti[i])) {
                    bestv[i] = d;
                    besti[i] = ix;
                }
            }
        }
    }

    // Cross-thread reduction over the 16 column groups.
    __syncthreads();
    #pragma unroll
    for (int i = 0; i < TM; i++) {
        redv[ty * TM + i][tx] = bestv[i];
        redi[ty * TM + i][tx] = besti[i];
    }
    __syncthreads();
    if (tid < BM) {
        float bv = redv[tid][0];
        int   bi = redi[tid][0];
        #pragma unroll
        for (int t = 1; t < 16; t++) {
            float v = redv[tid][t];
            int  ii = redi[tid][t];
            if (v < bv || (v == bv && ii < bi)) { bv = v; bi = ii; }
        }
        g_idx[m0 + tid] = bi;
        out_idx_f[m0 + tid] = (float)bi;
    }
}

// ---------------------------------------------------------------------------
// Kernel 3: gather quantized = embedding[idx] (straight-through output equals
// the gather numerically) + SSE accumulation for the loss.
// grid: M_TOTAL blocks of 64 threads (one float4 per thread).
// ---------------------------------------------------------------------------
__global__ void gather_loss_kernel(
    const float* __restrict__ Q,
    const float* __restrict__ E,
    float* __restrict__ out)
{
    __shared__ float warp_s[2];
    const int row = blockIdx.x;
    const int idx = g_idx[row];

    const float4* q = (const float4*)(Q + (size_t)row * K_DIM);
    const float4* e = (const float4*)(E + (size_t)idx * K_DIM);
    float4*       o = (float4*)(out + M_TOTAL + (size_t)row * K_DIM);

    const int t = threadIdx.x;          // 0..63
    float4 qv = q[t];
    float4 ev = e[t];
    o[t] = ev;

    float dx = qv.x - ev.x, dy = qv.y - ev.y, dz = qv.z - ev.z, dw = qv.w - ev.w;
    float s = dx * dx + dy * dy + dz * dz + dw * dw;

    #pragma unroll
    for (int off = 16; off > 0; off >>= 1)
        s += __shfl_down_sync(0xffffffffu, s, off);
    if ((t & 31) == 0) warp_s[t >> 5] = s;
    __syncthreads();
    if (t == 0) {
        atomicAdd(&g_loss, (double)(warp_s[0] + warp_s[1]));
    }
}

// ---------------------------------------------------------------------------
// Kernel 4: finalize loss. vq = codebook + 0.25*commit = 1.25 * SSE / NUMEL
// ---------------------------------------------------------------------------
__global__ void finalize_kernel(float* __restrict__ out) {
    out[M_TOTAL + (size_t)NUMEL] = (float)(1.25 * g_loss / (double)NUMEL);
}

// ---------------------------------------------------------------------------
extern "C" void kernel_launch(void* const* d_in, const int* in_sizes, int n_in,
                              void* d_out, int out_size) {
    const float* Q = (const float*)d_in[0];   // queries  [16,1024,256]
    const float* E = (const float*)d_in[1];   // embedding [8192,256]
    float* out = (float*)d_out;

    esq_kernel<<<N_CODES / 8, dim3(32, 8)>>>(E);
    qsq_kernel<<<M_TOTAL / 8, dim3(32, 8)>>>(Q);
    argmin_kernel<<<M_TOTAL / BM, NTHREADS>>>(Q, E, out);
    gather_loss_kernel<<<M_TOTAL, 64>>>(Q, E, out);
    finalize_kernel<<<1, 1>>>(out);
}

// round 4
// speedup vs baseline: 8.5231x; 8.5231x over previous
#include <cuda_runtime.h>
#include <cuda_bf16.h>

// ---------------------------------------------------------------------------
// Problem constants
// ---------------------------------------------------------------------------
#define M_TOTAL 16384   // 16 * 1024 query rows
#define N_CODES 8192
#define K_DIM   256
#define NUMEL   (M_TOTAL * K_DIM)   // 4194304

#define BM 128           // CTA M rows
#define BN 128           // codes per N-tile
#define NT_TILES (N_CODES / BN)     // 64
#define TOPK 4

// SMEM layout (dynamic)
#define SM_A     0                   // 128 x 256 bf16 swizzled = 64 KB
#define SM_B0    65536               // B tile buffer 0 = 64 KB
#define SM_B1    131072              // B tile buffer 1 = 64 KB
#define SM_ESQ0  196608              // 128 f32
#define SM_ESQ1  197120              // 128 f32
#define SM_CAND  65536               // alias B0 after main loop
#define SM_TOTAL 197632

// ---------------------------------------------------------------------------
// Scratch (no dynamic device allocation allowed)
// ---------------------------------------------------------------------------
__device__ float          g_esq[N_CODES];
__device__ float          g_qsq[M_TOTAL];
__device__ int            g_idx[M_TOTAL];
__device__ int            g_cand[M_TOTAL][TOPK];
__device__ unsigned short g_E_bf16[N_CODES * K_DIM];
__device__ unsigned short g_Q_bf16[M_TOTAL * K_DIM];
__device__ double         g_loss;

// ---------------------------------------------------------------------------
// Baseline-PTX helpers (no "a"-arch features: mma.sync / ldmatrix / cp.async)
// ---------------------------------------------------------------------------
__device__ __forceinline__ unsigned smem_u32(const void* p) {
    unsigned a;
    asm("{ .reg .u64 t; cvta.to.shared.u64 t, %1; cvt.u32.u64 %0, t; }"
        : "=r"(a) : "l"(p));
    return a;
}

#define LDSM_X4(r, addr) \
    asm volatile("ldmatrix.sync.aligned.m8n8.x4.shared.b16 {%0,%1,%2,%3}, [%4];" \
        : "=r"((r)[0]), "=r"((r)[1]), "=r"((r)[2]), "=r"((r)[3]) : "r"(addr))

#define MMA16816(c, a, b0, b1) \
    asm volatile("mma.sync.aligned.m16n8k16.row.col.f32.bf16.bf16.f32 " \
        "{%0,%1,%2,%3}, {%4,%5,%6,%7}, {%8,%9}, {%0,%1,%2,%3};" \
        : "+f"((c)[0]), "+f"((c)[1]), "+f"((c)[2]), "+f"((c)[3]) \
        : "r"((a)[0]), "r"((a)[1]), "r"((a)[2]), "r"((a)[3]), "r"(b0), "r"(b1))

__device__ __forceinline__ void cp16(unsigned dst, const void* src) {
    asm volatile("cp.async.cg.shared.global [%0], [%1], 16;"
                 :: "r"(dst), "l"(src));
}
#define CP_COMMIT()  asm volatile("cp.async.commit_group;" ::: "memory")
#define CP_WAIT_1()  asm volatile("cp.async.wait_group 1;" ::: "memory")
#define CP_WAIT_0()  asm volatile("cp.async.wait_group 0;" ::: "memory")

// ---------------------------------------------------------------------------
// Kernel 1a: e_sq[n] + zero loss accumulator
// ---------------------------------------------------------------------------
__global__ void esq_kernel(const float* __restrict__ emb) {
    if (blockIdx.x == 0 && threadIdx.x == 0 && threadIdx.y == 0) g_loss = 0.0;
    int row = blockIdx.x * 8 + threadIdx.y;
    const float* e = emb + (size_t)row * K_DIM;
    float s = 0.0f;
    #pragma unroll
    for (int j = 0; j < K_DIM / 32; j++) {
        float v = e[threadIdx.x + 32 * j];
        s = __fadd_rn(s, __fmul_rn(v, v));
    }
    #pragma unroll
    for (int o = 16; o > 0; o >>= 1)
        s = __fadd_rn(s, __shfl_down_sync(0xffffffffu, s, o));
    if (threadIdx.x == 0) g_esq[row] = s;
}

// ---------------------------------------------------------------------------
// Kernel 1b: q_sq[m] — XLA-order row reduction (bit-exact match, passed R2)
// ---------------------------------------------------------------------------
__global__ void qsq_kernel(const float* __restrict__ q) {
    int row = blockIdx.x * 8 + threadIdx.y;
    const float* x = q + (size_t)row * K_DIM;
    float s = 0.0f;
    #pragma unroll
    for (int j = 0; j < K_DIM / 32; j++) {
        float v = x[threadIdx.x + 32 * j];
        s = __fadd_rn(s, __fmul_rn(v, v));
    }
    #pragma unroll
    for (int o = 16; o > 0; o >>= 1)
        s = __fadd_rn(s, __shfl_down_sync(0xffffffffu, s, o));
    if (threadIdx.x == 0) g_qsq[row] = s;
}

// ---------------------------------------------------------------------------
// Kernel 1c/1d: f32 -> bf16 conversions for the tensor-core pass
// ---------------------------------------------------------------------------
__global__ void convert_e_kernel(const float* __restrict__ E) {
    int i = blockIdx.x * 256 + threadIdx.x;
    float2 v = ((const float2*)E)[i];
    __nv_bfloat162 b = __float22bfloat162_rn(v);
    ((__nv_bfloat162*)g_E_bf16)[i] = b;
}
__global__ void convert_q_kernel(const float* __restrict__ Q) {
    int i = blockIdx.x * 256 + threadIdx.x;
    float2 v = ((const float2*)Q)[i];
    __nv_bfloat162 b = __float22bfloat162_rn(v);
    ((__nv_bfloat162*)g_Q_bf16)[i] = b;
}

// ---------------------------------------------------------------------------
// Kernel 2: bf16 mma.sync GEMM + per-row candidate tracking.
// CTA: 128 query rows, 256 threads = 8 warps (2 M x 4 N), warp tile 64x32.
// approx dist(m,n) = esq[n] - 2*dot_bf16(q_m, e_n)   (qsq per-row constant).
// Each lane keeps exact top-2 (val,idx) per owned row; 16 lanes/row -> 32
// candidates merged in SMEM to top-4 -> g_cand.
// ---------------------------------------------------------------------------
__global__ __launch_bounds__(256, 1) void gemm_topk_kernel() {
    extern __shared__ char smem[];
    const unsigned sbase = smem_u32(smem);
    const int tid    = threadIdx.x;
    const int lane   = tid & 31;
    const int wid    = tid >> 5;
    const int warp_m = wid >> 2;          // 0..1
    const int warp_n = wid & 3;           // 0..3
    const int m0     = blockIdx.x * BM;

    // ---- stage A (swizzled granules: g' = g ^ (row&7), 16B granules) ----
    {
        const uint4* Aq = (const uint4*)(g_Q_bf16 + (size_t)m0 * K_DIM);
        #pragma unroll
        for (int it = 0; it < 16; it++) {
            int i   = it * 256 + tid;     // 4096 granules
            int row = i >> 5;
            int g   = i & 31;
            uint4 v = Aq[row * 32 + g];
            *(uint4*)(smem + SM_A + row * 512 + (((g ^ (row & 7)) << 4))) = v;
        }
    }

    // ---- B tile async loader ----
    auto issue_B = [&](int t, int buf) {
        const uint4* Bq = (const uint4*)(g_E_bf16 + (size_t)t * BN * K_DIM);
        unsigned bb = sbase + SM_B0 + buf * 65536;
        #pragma unroll
        for (int it = 0; it < 16; it++) {
            int i   = it * 256 + tid;
            int row = i >> 5;
            int g   = i & 31;
            cp16(bb + row * 512 + (((g ^ (row & 7)) << 4)), Bq + row * 32 + g);
        }
        if (tid < BN)
            *(float*)(smem + SM_ESQ0 + buf * 512 + tid * 4) = g_esq[t * BN + tid];
    };

    issue_B(0, 0);
    CP_COMMIT();

    // ldmatrix lane-invariant address pieces
    const int j       = lane >> 3;
    const int a_rloc  = (j & 1) * 8 + (lane & 7);   // row-in-16 for A frags
    const int a_khalf = (j >> 1);                   // k 8-half for A frags
    const int b_rloc  = (j >> 1) * 8 + (lane & 7);  // row-in-16 for B frags
    const int b_khalf = (j & 1);                    // k 8-half for B frags
    const unsigned aRowBase = sbase + SM_A + (unsigned)(warp_m * 64 + a_rloc) * 512;

    // per-lane, per-row top-2 (rows: r = mt*2 + hi -> warp_m*64+mt*16+hi*8+(lane>>2))
    float v1[8], v2[8];
    int   i1[8], i2[8];
    #pragma unroll
    for (int r = 0; r < 8; r++) { v1[r] = 3.4e38f; v2[r] = 3.4e38f; i1[r] = 0; i2[r] = 0; }

    for (int t = 0; t < NT_TILES; t++) {
        const int nb = t & 1;
        if (t + 1 < NT_TILES) {
            issue_B(t + 1, nb ^ 1);
            CP_COMMIT();
            CP_WAIT_1();
        } else {
            CP_WAIT_0();
        }
        __syncthreads();   // tile t visible everywhere; prev compute done

        const unsigned sB = sbase + SM_B0 + nb * 65536 + (unsigned)(warp_n * 32) * 512;
        const float* sE = (const float*)(smem + SM_ESQ0 + nb * 512);

        float acc[4][4][4];
        #pragma unroll
        for (int mt = 0; mt < 4; mt++)
            #pragma unroll
            for (int nt = 0; nt < 4; nt++)
                #pragma unroll
                for (int c = 0; c < 4; c++) acc[mt][nt][c] = 0.0f;

        #pragma unroll
        for (int ks = 0; ks < 16; ks++) {
            const unsigned swzA = (unsigned)(((2 * ks + a_khalf) ^ (lane & 7)) << 4);
            const unsigned swzB = (unsigned)(((2 * ks + b_khalf) ^ (lane & 7)) << 4);

            unsigned a[4][4];
            #pragma unroll
            for (int mt = 0; mt < 4; mt++)
                LDSM_X4(a[mt], aRowBase + (unsigned)(mt * 16) * 512 + swzA);

            unsigned b[2][4];   // b[nt2] covers n-tiles 2*nt2 ({r0,r1}) and 2*nt2+1 ({r2,r3})
            #pragma unroll
            for (int nt2 = 0; nt2 < 2; nt2++)
                LDSM_X4(b[nt2], sB + (unsigned)(nt2 * 16 + b_rloc) * 512 + swzB);

            #pragma unroll
            for (int mt = 0; mt < 4; mt++) {
                MMA16816(acc[mt][0], a[mt], b[0][0], b[0][1]);
                MMA16816(acc[mt][1], a[mt], b[0][2], b[0][3]);
                MMA16816(acc[mt][2], a[mt], b[1][0], b[1][1]);
                MMA16816(acc[mt][3], a[mt], b[1][2], b[1][3]);
            }
        }

        // ---- epilogue: top-2 tracking ----
        #pragma unroll
        for (int nt = 0; nt < 4; nt++) {
            const int cbase = warp_n * 32 + nt * 8 + ((lane & 3) << 1);
            const float e0 = sE[cbase];
            const float e1 = sE[cbase + 1];
            const int n0 = t * BN + cbase;
            #pragma unroll
            for (int mt = 0; mt < 4; mt++) {
                #pragma unroll
                for (int c = 0; c < 4; c++) {
                    const int r  = mt * 2 + (c >> 1);       // hi = c>>1
                    const float d = fmaf(acc[mt][nt][c], -2.0f, (c & 1) ? e1 : e0);
                    const int  n  = n0 + (c & 1);
                    if (d < v2[r]) {
                        if (d < v1[r]) {
                            v2[r] = v1[r]; i2[r] = i1[r];
                            v1[r] = d;     i1[r] = n;
                        } else {
                            v2[r] = d;     i2[r] = n;
                        }
                    }
                }
            }
        }
        __syncthreads();   // done reading sB/sE before next overwrite
    }

    // ---- merge: 32 candidates/row -> top-4 ----
    float* cv = (float*)(smem + SM_CAND);          // [128][32]
    int*   ci = (int*)(smem + SM_CAND + 16384);    // [128][32]
    #pragma unroll
    for (int r = 0; r < 8; r++) {
        const int mt = r >> 1, hi = r & 1;
        const int row  = warp_m * 64 + mt * 16 + hi * 8 + (lane >> 2);
        const int slot = warp_n * 8 + (lane & 3) * 2;
        cv[row * 32 + slot]     = v1[r];  ci[row * 32 + slot]     = i1[r];
        cv[row * 32 + slot + 1] = v2[r];  ci[row * 32 + slot + 1] = i2[r];
    }
    __syncthreads();
    if (tid < BM) {
        const int row = tid;
        float bv[4] = {3.4e38f, 3.4e38f, 3.4e38f, 3.4e38f};
        int   bi[4] = {0, 0, 0, 0};
        #pragma unroll 4
        for (int s = 0; s < 32; s++) {
            const float v = cv[row * 32 + s];
            const int   n = ci[row * 32 + s];
            if (v < bv[3]) {
                if (v < bv[2]) {
                    bv[3] = bv[2]; bi[3] = bi[2];
                    if (v < bv[1]) {
                        bv[2] = bv[1]; bi[2] = bi[1];
                        if (v < bv[0]) {
                            bv[1] = bv[0]; bi[1] = bi[0];
                            bv[0] = v; bi[0] = n;
                        } else { bv[1] = v; bi[1] = n; }
                    } else { bv[2] = v; bi[2] = n; }
                } else { bv[3] = v; bi[3] = n; }
            }
        }
        #pragma unroll
        for (int c = 0; c < TOPK; c++) g_cand[m0 + row][c] = bi[c];
    }
}

// ---------------------------------------------------------------------------
// Kernel 3: exact refine of TOPK candidates (round-2 bit-exact arithmetic:
// ascending-k fmaf, reference f32 grid emulation, lowest-index tie-break).
// ---------------------------------------------------------------------------
__global__ __launch_bounds__(128) void refine_kernel(
    const float* __restrict__ Q,
    const float* __restrict__ E,
    float* __restrict__ out_idx_f)
{
    int row = blockIdx.x * 128 + threadIdx.x;
    float qs = g_qsq[row];
    const float4* q = (const float4*)(Q + (size_t)row * K_DIM);
    float bestd = 3.4e38f;
    int   besti = 0x7fffffff;
    #pragma unroll
    for (int c = 0; c < TOPK; c++) {
        int n = g_cand[row][c];
        const float4* e = (const float4*)(E + (size_t)n * K_DIM);
        float acc = 0.0f;
        #pragma unroll 8
        for (int k = 0; k < K_DIM / 4; k++) {
            float4 qv = q[k];
            float4 ev = e[k];
            acc = fmaf(qv.x, ev.x, acc);
            acc = fmaf(qv.y, ev.y, acc);
            acc = fmaf(qv.z, ev.z, acc);
            acc = fmaf(qv.w, ev.w, acc);
        }
        float d = __fsub_rn(__fadd_rn(qs, g_esq[n]), 2.0f * acc);
        if (d < bestd || (d == bestd && n < besti)) { bestd = d; besti = n; }
    }
    g_idx[row] = besti;
    out_idx_f[row] = (float)besti;
}

// ---------------------------------------------------------------------------
// Kernel 4: gather quantized = embedding[idx] + SSE for the loss.
// ---------------------------------------------------------------------------
__global__ __launch_bounds__(256) void gather_loss_kernel(
    const float* __restrict__ Q,
    const float* __restrict__ E,
    float* __restrict__ out)
{
    __shared__ float warp_s[8];
    const int r   = threadIdx.x >> 6;
    const int t   = threadIdx.x & 63;
    const int row = blockIdx.x * 4 + r;
    const int idx = g_idx[row];

    const float4* q = (const float4*)(Q + (size_t)row * K_DIM);
    const float4* e = (const float4*)(E + (size_t)idx * K_DIM);
    float4*       o = (float4*)(out + M_TOTAL + (size_t)row * K_DIM);

    float4 qv = q[t];
    float4 ev = e[t];
    o[t] = ev;

    float dx = qv.x - ev.x, dy = qv.y - ev.y, dz = qv.z - ev.z, dw = qv.w - ev.w;
    float s = dx * dx + dy * dy + dz * dz + dw * dw;

    #pragma unroll
    for (int off = 16; off > 0; off >>= 1)
        s += __shfl_down_sync(0xffffffffu, s, off);
    if ((threadIdx.x & 31) == 0) warp_s[threadIdx.x >> 5] = s;
    __syncthreads();
    if (threadIdx.x == 0) {
        float acc = 0.0f;
        #pragma unroll
        for (int w = 0; w < 8; w++) acc += warp_s[w];
        atomicAdd(&g_loss, (double)acc);
    }
}

// ---------------------------------------------------------------------------
// Kernel 5: finalize loss. vq = codebook + 0.25*commit = 1.25 * SSE / NUMEL
// ---------------------------------------------------------------------------
__global__ void finalize_kernel(float* __restrict__ out) {
    out[M_TOTAL + (size_t)NUMEL] = (float)(1.25 * g_loss / (double)NUMEL);
}

// ---------------------------------------------------------------------------
extern "C" void kernel_launch(void* const* d_in, const int* in_sizes, int n_in,
                              void* d_out, int out_size) {
    const float* Q = (const float*)d_in[0];   // queries   [16,1024,256]
    const float* E = (const float*)d_in[1];   // embedding [8192,256]
    float* out = (float*)d_out;

    static int configured = 0;
    if (!configured) {
        cudaFuncSetAttribute(gemm_topk_kernel,
                             cudaFuncAttributeMaxDynamicSharedMemorySize, SM_TOTAL);
        configured = 1;
    }

    esq_kernel<<<N_CODES / 8, dim3(32, 8)>>>(E);
    qsq_kernel<<<M_TOTAL / 8, dim3(32, 8)>>>(Q);
    convert_e_kernel<<<(N_CODES * K_DIM / 2) / 256, 256>>>(E);
    convert_q_kernel<<<(M_TOTAL * K_DIM / 2) / 256, 256>>>(Q);
    gemm_topk_kernel<<<M_TOTAL / BM, 256, SM_TOTAL>>>();
    refine_kernel<<<M_TOTAL / 128, 128>>>(Q, E, out);
    gather_loss_kernel<<<M_TOTAL / 4, 256>>>(Q, E, out);
    finalize_kernel<<<1, 1>>>(out);
}